// round 16
// baseline (speedup 1.0000x reference)
#include <cuda_runtime.h>

// ---------------------------------------------------------------------------
// SSIM loss, fused strip kernel, ring-buffered horizontal-blur planes,
// gmem-direct stage A, 6 blocks/SM, 4-field algebraic reduction.
// Key identity: denominator needs only blur(a^2)+blur(b^2), numerator only
// blur(ab).  With P = blur((a+b)^2), M = blur((a-b)^2):
//   blur(a^2+b^2) = (P+M)/2,  blur(ab) = (P-M)/4.
// So we blur 4 fields {a, b, (a+b)^2, (a-b)^2} -> 4 H planes, 32.8 KB smem,
// which now fits SIX blocks/SM (196.8 KB of 227 KB); launch_bounds caps
// registers at 42 to make 1536 threads/SM legal.
// Block owns a 64 (x) x 256 (y) strip, processed as 16 chunks of 16 rows.
// H: 4 scalar planes [32][64] ring keyed by (gy & 31); HSTRIDE=64 (shifts).
// Stage A: horizontal 11-tap blur, 4-col register runs, gmem float4 direct.
// Stage B: vertical 11-tap blur + ssim epilogue, 4-row runs; 4 fractions
//          combine rationally -> ONE __fdividef per chunk.
// Reduce: warp shuffle -> block -> atomicAdd(double); counter-elected last
//         block writes 1 - mean and resets accumulators (replay-safe).
// ---------------------------------------------------------------------------

#define NTHREADS 256
#define TX 64
#define TY 16            // rows per chunk
#define NCHUNK 16        // chunks per strip
#define SY (TY * NCHUNK) // 256 rows per strip
#define HROWS 32         // ring rows (power of 2)
#define HSTRIDE 64       // H row stride (floats), power of 2
#define IMG 1024
#define NBLOCKS (16 * 4 * 32)

#define PLANEF (HROWS * HSTRIDE)
#define SMEM_FLOATS (4 * PLANEF + 8)
#define SMEM_BYTES (SMEM_FLOATS * 4)     // 32,800 B -> 6 blocks/SM

static __device__ __forceinline__ float Wt(int t) {
    // Gaussian, WIN=11, SIGMA=1.5, normalized; compile-time constants so
    // ptxas emits FFMA-imm (rt_SMSP=1, 2x tput vs 3-reg FFMA).
    constexpr float w[6] = {0.00102838f, 0.00759875f, 0.03600077f,
                            0.10936069f, 0.21300553f, 0.26601172f};
    return (t < 6) ? w[t] : w[10 - t];
}

__device__ double g_acc = 0.0;
__device__ unsigned g_count = 0u;

__global__ __launch_bounds__(NTHREADS, 6)
void ssim_main(const float* __restrict__ img1, const float* __restrict__ img2,
               float* __restrict__ out) {
    extern __shared__ float smem[];
    float* H    = smem;                 // [4][HROWS][HSTRIDE] ring
    float* wsum = smem + 4 * PLANEF;    // [8]

    const float C1f = 0.0004f;   // (0.01*2)^2
    const float C2f = 0.0036f;   // (0.03*2)^2

    const int tid = threadIdx.x;
    const int tx0 = blockIdx.x * TX;
    const int sy0 = blockIdx.y * SY;
    const size_t base = (size_t)blockIdx.z * (size_t)(IMG * IMG);
    const bool xedge = (blockIdx.x == 0) | (blockIdx.x == (IMG / TX - 1));

    float lsum = 0.f;

    #pragma unroll 1
    for (int ch = 0; ch < NCHUNK; ch++) {
        const int y0c = sy0 + ch * TY;   // first output row of this chunk

        if (ch > 0) __syncthreads();     // stage B readers done before slot reuse

        // -------- Stage A: horizontal blur of new rows into ring ------------
        // chunk 0: 26 rows (gy in [y0c-5, y0c+21)), 416 jobs (2 passes);
        // steady : 16 rows (gy in [y0c+5, y0c+21)), 256 jobs (1 pass).
        const int nrows  = (ch == 0) ? 26 : TY;
        const int row_lo = (ch == 0) ? -5 : 5;
        for (int j = tid; j < nrows * 16; j += NTHREADS) {
            const int r  = j >> 4;
            const int c0 = (j & 15) * 4;            // output cols c0..c0+3
            const int gy = y0c + row_lo + r;
            const int slot = gy & (HROWS - 1);

            float acc[4][4];
            #pragma unroll
            for (int f = 0; f < 4; f++)
                #pragma unroll
                for (int i = 0; i < 4; i++) acc[f][i] = 0.f;

            if ((unsigned)gy < (unsigned)IMG) {
                const size_t rowo = base + (size_t)gy * IMG;
                const int gx0 = tx0 - 8 + c0;       // window start (aligned 4)
                if (!xedge) {
                    #pragma unroll
                    for (int q = 0; q < 5; q++) {
                        const float4 v1 = *reinterpret_cast<const float4*>(
                            img1 + rowo + gx0 + 4 * q);
                        const float4 v2 = *reinterpret_cast<const float4*>(
                            img2 + rowo + gx0 + 4 * q);
                        const float a4[4] = {v1.x, v1.y, v1.z, v1.w};
                        const float b4[4] = {v2.x, v2.y, v2.z, v2.w};
                        #pragma unroll
                        for (int i = 0; i < 4; i++) {
                            const int k = 4 * q + i - 3;   // tap window index
                            if (k >= 0 && k < 14) {
                                const float a = a4[i];
                                const float b = b4[i];
                                const float p = a + b;
                                const float m = a - b;
                                const float pp = p * p;
                                const float mm = m * m;
                                #pragma unroll
                                for (int jj = 0; jj < 4; jj++) {
                                    const int t = k - jj;
                                    if (t >= 0 && t <= 10) {
                                        const float w = Wt(t);
                                        acc[0][jj] += w * a;
                                        acc[1][jj] += w * b;
                                        acc[2][jj] += w * pp;
                                        acc[3][jj] += w * mm;
                                    }
                                }
                            }
                        }
                    }
                } else {
                    // edge blocks: predicated scalar loads (2/16 of grid.x)
                    #pragma unroll
                    for (int q = 0; q < 5; q++) {
                        #pragma unroll
                        for (int i = 0; i < 4; i++) {
                            const int k = 4 * q + i - 3;
                            if (k >= 0 && k < 14) {
                                const int gx = gx0 + 4 * q + i;
                                float a = 0.f, b = 0.f;
                                if ((unsigned)gx < (unsigned)IMG) {
                                    a = __ldg(img1 + rowo + gx);
                                    b = __ldg(img2 + rowo + gx);
                                }
                                const float p = a + b;
                                const float m = a - b;
                                const float pp = p * p;
                                const float mm = m * m;
                                #pragma unroll
                                for (int jj = 0; jj < 4; jj++) {
                                    const int t = k - jj;
                                    if (t >= 0 && t <= 10) {
                                        const float w = Wt(t);
                                        acc[0][jj] += w * a;
                                        acc[1][jj] += w * b;
                                        acc[2][jj] += w * pp;
                                        acc[3][jj] += w * mm;
                                    }
                                }
                            }
                        }
                    }
                }
            }
            const int so = (slot << 6) + c0;   // slot * HSTRIDE + c0
            float* hp = H + so;
            #pragma unroll
            for (int f = 0; f < 4; f++) {
                *reinterpret_cast<float4*>(hp) =
                    make_float4(acc[f][0], acc[f][1], acc[f][2], acc[f][3]);
                hp += PLANEF;
            }
        }
        __syncthreads();

        // -------- Stage B: vertical blur + ssim, 4 rows per thread ---------
        {
            const int c  = tid & (TX - 1);        // output column 0..63
            const int g4 = (tid >> 6) * 4;        // first output row in chunk
            const int b0 = y0c - 5 + g4;          // first tap's absolute row
            const float* hb = H + c;
            float v[4][4];
            #pragma unroll
            for (int f = 0; f < 4; f++)
                #pragma unroll
                for (int i = 0; i < 4; i++) v[f][i] = 0.f;

            #pragma unroll
            for (int k = 0; k < 14; k++) {
                const int off = ((b0 + k) & (HROWS - 1)) << 6;  // * HSTRIDE
                const float* hk = hb + off;
                float h[4];
                #pragma unroll
                for (int f = 0; f < 4; f++) {
                    h[f] = *hk;
                    hk += PLANEF;
                }
                #pragma unroll
                for (int jj = 0; jj < 4; jj++) {
                    const int t = k - jj;
                    if (t >= 0 && t <= 10) {
                        const float w = Wt(t);
                        #pragma unroll
                        for (int f = 0; f < 4; f++) v[f][jj] += w * h[f];
                    }
                }
            }

            // ssim fractions from 4 fields; combine rationally -> ONE divide.
            float Nn[4], Dd[4];
            #pragma unroll
            for (int jj = 0; jj < 4; jj++) {
                const float mu1 = v[0][jj];
                const float mu2 = v[1][jj];
                const float P   = v[2][jj];       // blur((a+b)^2)
                const float M   = v[3][jj];       // blur((a-b)^2)
                const float mu12 = mu1 * mu2;
                const float mu1s = mu1 * mu1;
                const float mu2s = mu2 * mu2;
                const float sumsq = 0.5f * (P + M);    // blur(a^2)+blur(b^2)
                const float abv   = 0.25f * (P - M);   // blur(ab)
                const float s12   = abv - mu12;
                const float musum = mu1s + mu2s;
                Nn[jj] = (2.f * mu12 + C1f) * (2.f * s12 + C2f);
                Dd[jj] = (musum + C1f) * (sumsq - musum + C2f);
            }
            const float n01 = Nn[0] * Dd[1] + Nn[1] * Dd[0];
            const float d01 = Dd[0] * Dd[1];
            const float n23 = Nn[2] * Dd[3] + Nn[3] * Dd[2];
            const float d23 = Dd[2] * Dd[3];
            lsum += __fdividef(n01 * d23 + n23 * d01, d01 * d23);
        }
    }

    // -------- Reduction ----------------------------------------------------
    #pragma unroll
    for (int o = 16; o > 0; o >>= 1)
        lsum += __shfl_xor_sync(0xffffffffu, lsum, o);
    if ((tid & 31) == 0) wsum[tid >> 5] = lsum;
    __syncthreads();
    if (tid == 0) {
        float bs = 0.f;
        #pragma unroll
        for (int w = 0; w < 8; w++) bs += wsum[w];
        atomicAdd(&g_acc, (double)bs);
        __threadfence();
        const unsigned old = atomicAdd(&g_count, 1u);
        if (old == NBLOCKS - 1) {
            const double s = *((volatile double*)&g_acc);
            out[0] = (float)(1.0 - s * (1.0 / 33554432.0));  // 32*1024*1024
            *((volatile double*)&g_acc) = 0.0;
            __threadfence();
            atomicExch(&g_count, 0u);
        }
    }
}

extern "C" void kernel_launch(void* const* d_in, const int* in_sizes, int n_in,
                              void* d_out, int out_size) {
    (void)in_sizes; (void)n_in; (void)out_size;
    const float* img1 = (const float*)d_in[0];
    const float* img2 = (const float*)d_in[1];
    float* out = (float*)d_out;

    static int smem_set = 0;
    if (!smem_set) {
        cudaFuncSetAttribute(ssim_main,
                             cudaFuncAttributeMaxDynamicSharedMemorySize,
                             SMEM_BYTES);
        smem_set = 1;
    }

    dim3 grid(IMG / TX, IMG / SY, 32);   // 16 x 4 x 32 = 2048 blocks
    ssim_main<<<grid, NTHREADS, SMEM_BYTES>>>(img1, img2, out);
}

// round 17
// speedup vs baseline: 1.1550x; 1.1550x over previous
#include <cuda_runtime.h>

// ---------------------------------------------------------------------------
// SSIM loss, fused strip kernel, ring-buffered horizontal-blur planes,
// gmem-direct stage A, 5 blocks/SM, 4-field algebraic reduction.
// Key identity: denominator needs only blur(a^2)+blur(b^2), numerator only
// blur(ab).  With P = blur((a+b)^2), M = blur((a-b)^2):
//   blur(a^2+b^2) = (P+M)/2,  blur(ab) = (P-M)/4.
// Blur fields: {a, b, (a+b)^2, (a-b)^2} -> 4 H planes, 32.8 KB smem.
// 5 blocks/SM (R15 showed 6 blocks forces regs 48->40 and regresses:
// issue% falls faster than occupancy rises; 5 is the right point).
// Block owns a 64 (x) x 256 (y) strip, processed as 16 chunks of 16 rows.
// H: 4 scalar planes [32][64] ring keyed by (gy & 31); HSTRIDE=64 (shifts).
// Stage A: horizontal 11-tap blur, 4-col register runs, gmem float4 direct;
//          steady-state chunks have EXACTLY 256 jobs -> straight-line path
//          (no grid-stride loop), only chunk 0 loops (416 jobs).
// Stage B: vertical 11-tap blur + ssim epilogue, 4-row runs; 4 fractions
//          combine rationally -> ONE __fdividef per chunk.
// Reduce: warp shuffle -> block -> atomicAdd(double); counter-elected last
//         block writes 1 - mean and resets accumulators (replay-safe).
// ---------------------------------------------------------------------------

#define NTHREADS 256
#define TX 64
#define TY 16            // rows per chunk
#define NCHUNK 16        // chunks per strip
#define SY (TY * NCHUNK) // 256 rows per strip
#define HROWS 32         // ring rows (power of 2)
#define HSTRIDE 64       // H row stride (floats), power of 2
#define IMG 1024
#define NBLOCKS (16 * 4 * 32)

#define PLANEF (HROWS * HSTRIDE)
#define SMEM_FLOATS (4 * PLANEF + 8)
#define SMEM_BYTES (SMEM_FLOATS * 4)     // 32,800 B -> 5 blocks/SM

static __device__ __forceinline__ float Wt(int t) {
    // Gaussian, WIN=11, SIGMA=1.5, normalized; compile-time constants so
    // ptxas emits FFMA-imm (rt_SMSP=1, 2x tput vs 3-reg FFMA).
    constexpr float w[6] = {0.00102838f, 0.00759875f, 0.03600077f,
                            0.10936069f, 0.21300553f, 0.26601172f};
    return (t < 6) ? w[t] : w[10 - t];
}

__device__ double g_acc = 0.0;
__device__ unsigned g_count = 0u;

// One stage-A job: horizontal blur of 4 output columns of one row into the
// ring.  nk = number of valid tap-window positions (14 steady, 14 chunk-0
// too since each job covers 4 cols); kept as template-free constant 14.
static __device__ __forceinline__ void stageA_job(
    const float* __restrict__ img1, const float* __restrict__ img2,
    float* __restrict__ H, size_t base, int tx0, bool xedge,
    int gy, int c0) {

    const int slot = gy & (HROWS - 1);
    float acc[4][4];
    #pragma unroll
    for (int f = 0; f < 4; f++)
        #pragma unroll
        for (int i = 0; i < 4; i++) acc[f][i] = 0.f;

    if ((unsigned)gy < (unsigned)IMG) {
        const size_t rowo = base + (size_t)gy * IMG;
        const int gx0 = tx0 - 8 + c0;       // window start (aligned 4)
        if (!xedge) {
            #pragma unroll
            for (int q = 0; q < 5; q++) {
                const float4 v1 = *reinterpret_cast<const float4*>(
                    img1 + rowo + gx0 + 4 * q);
                const float4 v2 = *reinterpret_cast<const float4*>(
                    img2 + rowo + gx0 + 4 * q);
                const float a4[4] = {v1.x, v1.y, v1.z, v1.w};
                const float b4[4] = {v2.x, v2.y, v2.z, v2.w};
                #pragma unroll
                for (int i = 0; i < 4; i++) {
                    const int k = 4 * q + i - 3;   // tap window index
                    if (k >= 0 && k < 14) {
                        const float a = a4[i];
                        const float b = b4[i];
                        const float p = a + b;
                        const float m = a - b;
                        const float pp = p * p;
                        const float mm = m * m;
                        #pragma unroll
                        for (int jj = 0; jj < 4; jj++) {
                            const int t = k - jj;
                            if (t >= 0 && t <= 10) {
                                const float w = Wt(t);
                                acc[0][jj] += w * a;
                                acc[1][jj] += w * b;
                                acc[2][jj] += w * pp;
                                acc[3][jj] += w * mm;
                            }
                        }
                    }
                }
            }
        } else {
            // edge blocks: predicated scalar loads (2/16 of grid.x)
            #pragma unroll
            for (int q = 0; q < 5; q++) {
                #pragma unroll
                for (int i = 0; i < 4; i++) {
                    const int k = 4 * q + i - 3;
                    if (k >= 0 && k < 14) {
                        const int gx = gx0 + 4 * q + i;
                        float a = 0.f, b = 0.f;
                        if ((unsigned)gx < (unsigned)IMG) {
                            a = __ldg(img1 + rowo + gx);
                            b = __ldg(img2 + rowo + gx);
                        }
                        const float p = a + b;
                        const float m = a - b;
                        const float pp = p * p;
                        const float mm = m * m;
                        #pragma unroll
                        for (int jj = 0; jj < 4; jj++) {
                            const int t = k - jj;
                            if (t >= 0 && t <= 10) {
                                const float w = Wt(t);
                                acc[0][jj] += w * a;
                                acc[1][jj] += w * b;
                                acc[2][jj] += w * pp;
                                acc[3][jj] += w * mm;
                            }
                        }
                    }
                }
            }
        }
    }
    const int so = (slot << 6) + c0;   // slot * HSTRIDE + c0
    float* hp = H + so;
    #pragma unroll
    for (int f = 0; f < 4; f++) {
        *reinterpret_cast<float4*>(hp) =
            make_float4(acc[f][0], acc[f][1], acc[f][2], acc[f][3]);
        hp += PLANEF;
    }
}

__global__ __launch_bounds__(NTHREADS, 5)
void ssim_main(const float* __restrict__ img1, const float* __restrict__ img2,
               float* __restrict__ out) {
    extern __shared__ float smem[];
    float* H    = smem;                 // [4][HROWS][HSTRIDE] ring
    float* wsum = smem + 4 * PLANEF;    // [8]

    const float C1f = 0.0004f;   // (0.01*2)^2
    const float C2f = 0.0036f;   // (0.03*2)^2

    const int tid = threadIdx.x;
    const int tx0 = blockIdx.x * TX;
    const int sy0 = blockIdx.y * SY;
    const size_t base = (size_t)blockIdx.z * (size_t)(IMG * IMG);
    const bool xedge = (blockIdx.x == 0) | (blockIdx.x == (IMG / TX - 1));

    float lsum = 0.f;

    // -------- chunk 0 prologue: 26 rows, 416 jobs (grid-stride) ------------
    {
        const int y0c = sy0;
        for (int j = tid; j < 26 * 16; j += NTHREADS) {
            const int r  = j >> 4;
            const int c0 = (j & 15) * 4;
            stageA_job(img1, img2, H, base, tx0, xedge, y0c - 5 + r, c0);
        }
    }
    __syncthreads();

    #pragma unroll 1
    for (int ch = 0; ch < NCHUNK; ch++) {
        const int y0c = sy0 + ch * TY;   // first output row of this chunk

        // -------- Stage B: vertical blur + ssim, 4 rows per thread ---------
        {
            const int c  = tid & (TX - 1);        // output column 0..63
            const int g4 = (tid >> 6) * 4;        // first output row in chunk
            const int b0 = y0c - 5 + g4;          // first tap's absolute row
            const float* hb = H + c;
            float v[4][4];
            #pragma unroll
            for (int f = 0; f < 4; f++)
                #pragma unroll
                for (int i = 0; i < 4; i++) v[f][i] = 0.f;

            #pragma unroll
            for (int k = 0; k < 14; k++) {
                const int off = ((b0 + k) & (HROWS - 1)) << 6;  // * HSTRIDE
                const float* hk = hb + off;
                float h[4];
                #pragma unroll
                for (int f = 0; f < 4; f++) {
                    h[f] = *hk;
                    hk += PLANEF;
                }
                #pragma unroll
                for (int jj = 0; jj < 4; jj++) {
                    const int t = k - jj;
                    if (t >= 0 && t <= 10) {
                        const float w = Wt(t);
                        #pragma unroll
                        for (int f = 0; f < 4; f++) v[f][jj] += w * h[f];
                    }
                }
            }

            // ssim fractions from 4 fields; combine rationally -> ONE divide.
            float Nn[4], Dd[4];
            #pragma unroll
            for (int jj = 0; jj < 4; jj++) {
                const float mu1 = v[0][jj];
                const float mu2 = v[1][jj];
                const float P   = v[2][jj];       // blur((a+b)^2)
                const float M   = v[3][jj];       // blur((a-b)^2)
                const float mu12 = mu1 * mu2;
                const float mu1s = mu1 * mu1;
                const float mu2s = mu2 * mu2;
                const float sumsq = 0.5f * (P + M);    // blur(a^2)+blur(b^2)
                const float abv   = 0.25f * (P - M);   // blur(ab)
                const float s12   = abv - mu12;
                const float musum = mu1s + mu2s;
                Nn[jj] = (2.f * mu12 + C1f) * (2.f * s12 + C2f);
                Dd[jj] = (musum + C1f) * (sumsq - musum + C2f);
            }
            const float n01 = Nn[0] * Dd[1] + Nn[1] * Dd[0];
            const float d01 = Dd[0] * Dd[1];
            const float n23 = Nn[2] * Dd[3] + Nn[3] * Dd[2];
            const float d23 = Dd[2] * Dd[3];
            lsum += __fdividef(n01 * d23 + n23 * d01, d01 * d23);
        }

        // -------- Stage A for next chunk: 16 rows, exactly 256 jobs --------
        if (ch + 1 < NCHUNK) {
            __syncthreads();   // stage B readers done before slot reuse
            const int yn = sy0 + (ch + 1) * TY;
            const int r  = tid >> 4;
            const int c0 = (tid & 15) * 4;
            stageA_job(img1, img2, H, base, tx0, xedge, yn + 5 + r, c0);
            __syncthreads();
        }
    }

    // -------- Reduction ----------------------------------------------------
    #pragma unroll
    for (int o = 16; o > 0; o >>= 1)
        lsum += __shfl_xor_sync(0xffffffffu, lsum, o);
    if ((tid & 31) == 0) wsum[tid >> 5] = lsum;
    __syncthreads();
    if (tid == 0) {
        float bs = 0.f;
        #pragma unroll
        for (int w = 0; w < 8; w++) bs += wsum[w];
        atomicAdd(&g_acc, (double)bs);
        __threadfence();
        const unsigned old = atomicAdd(&g_count, 1u);
        if (old == NBLOCKS - 1) {
            const double s = *((volatile double*)&g_acc);
            out[0] = (float)(1.0 - s * (1.0 / 33554432.0));  // 32*1024*1024
            *((volatile double*)&g_acc) = 0.0;
            __threadfence();
            atomicExch(&g_count, 0u);
        }
    }
}

extern "C" void kernel_launch(void* const* d_in, const int* in_sizes, int n_in,
                              void* d_out, int out_size) {
    (void)in_sizes; (void)n_in; (void)out_size;
    const float* img1 = (const float*)d_in[0];
    const float* img2 = (const float*)d_in[1];
    float* out = (float*)d_out;

    static int smem_set = 0;
    if (!smem_set) {
        cudaFuncSetAttribute(ssim_main,
                             cudaFuncAttributeMaxDynamicSharedMemorySize,
                             SMEM_BYTES);
        smem_set = 1;
    }

    dim3 grid(IMG / TX, IMG / SY, 32);   // 16 x 4 x 32 = 2048 blocks
    ssim_main<<<grid, NTHREADS, SMEM_BYTES>>>(img1, img2, out);
}